// round 10
// baseline (speedup 1.0000x reference)
#include <cuda_runtime.h>
#include <cstdint>

#define SEQ     512
#define BATCH   64
#define HID     1024
#define TWOH    2048
#define NLAYER  2
#define NDEPTH  4

#define GRID    128      // CTAs; each owns 8 hidden columns (+ paired gate cols)
#define NTH     256
#define KC      32       // K-chunk
#define CPC     8        // h-columns per CTA  (HID / GRID)

// ---------------- device scratch (no cudaMalloc allowed) ----------------
__device__ float    g_S[NLAYER][2][BATCH * HID];   // double-buffered state
__device__ unsigned g_bar_count;
__device__ unsigned g_bar_gen;

// ---------------- software grid barrier (128 co-resident CTAs) ----------
__device__ __forceinline__ void grid_barrier() {
    __syncthreads();
    if (threadIdx.x == 0) {
        __threadfence();                         // publish this CTA's stores
        volatile unsigned* genp = &g_bar_gen;
        unsigned gen = *genp;
        if (atomicAdd(&g_bar_count, 1u) == GRID - 1u) {
            atomicExch(&g_bar_count, 0u);
            __threadfence();
            atomicExch(&g_bar_gen, gen + 1u);    // release
        } else {
            while (*genp == gen) { __nanosleep(40); }
            __threadfence();                     // acquire
        }
    }
    __syncthreads();
}

// ---------------- one GEMM accumulation pass: acc += A[64,1024] @ W cols --
// CTA c owns 16 weight columns: h-cols [c*8, c*8+8) and g-cols [1024+c*8, ...).
// Thread (r = tid&63, g4 = tid>>6) accumulates row r, 4 columns (g4*4..+3).
__device__ __forceinline__ void gemm_acc(
    const float* __restrict__ A,       // [64, 1024]  (state / input; read via .cg)
    const float* __restrict__ W,       // [1024, 2048] row-major
    float* s_sm, float* w_sm,
    int c, int tid, float4& acc)
{
    const int lrow = tid >> 2;          // 0..63 : row this thread loads for s-tile
    const int lq8  = (tid & 3) * 8;     // 8-float segment within 32-float k-chunk
    const int r    = tid & 63;
    const int g4   = tid >> 6;

    // W tile load mapping: 32 k × 16 n, 2 consecutive n per thread
    const int wk = tid >> 3;            // (tid*2)/16 = k row 0..31
    const int wn = (tid * 2) & 15;      // 0,2,..,14
    const int wcol = (wn < 8) ? (c * CPC + wn) : (HID + c * CPC + (wn - 8));

    const float* arow = s_sm + r * 33;
    const float* wqp  = w_sm + g4 * 4;

#pragma unroll 1
    for (int k0 = 0; k0 < HID; k0 += KC) {
        // stage next tiles (A must bypass L1: written by other SMs last step)
        float4 a0 = __ldcg((const float4*)(A + lrow * HID + k0 + lq8));
        float4 a1 = __ldcg((const float4*)(A + lrow * HID + k0 + lq8 + 4));
        float2 wv = *(const float2*)(W + (size_t)(k0 + wk) * TWOH + wcol);
        __syncthreads();                // previous chunk's reads done
        float* sd = s_sm + lrow * 33 + lq8;
        sd[0] = a0.x; sd[1] = a0.y; sd[2] = a0.z; sd[3] = a0.w;
        sd[4] = a1.x; sd[5] = a1.y; sd[6] = a1.z; sd[7] = a1.w;
        w_sm[wk * 16 + wn]     = wv.x;
        w_sm[wk * 16 + wn + 1] = wv.y;
        __syncthreads();
#pragma unroll
        for (int kk = 0; kk < KC; kk++) {
            float a = arow[kk];                              // conflict-free (pad 33)
            const float4 wq = *(const float4*)(wqp + kk * 16); // broadcast LDS.128
            acc.x = fmaf(a, wq.x, acc.x);
            acc.y = fmaf(a, wq.y, acc.y);
            acc.z = fmaf(a, wq.z, acc.z);
            acc.w = fmaf(a, wq.w, acc.w);
        }
    }
}

// ---------------- persistent RHN kernel ---------------------------------
__global__ void __launch_bounds__(NTH) rhn_kernel(
    const float* __restrict__ x,     // [512, 64, 1024]
    const float* __restrict__ st0,   // [2, 64, 1024]
    const float* __restrict__ w_in,  // [2, 1024, 2048]
    const float* __restrict__ w_h,   // [2, 4, 1024, 2048]
    const float* __restrict__ b_h,   // [2, 4, 2048]
    float* __restrict__ out)         // [512,64,1024] ++ [2,64,1024]
{
    __shared__ float s_sm[64 * 33];
    __shared__ float w_sm[KC * 16];
    __shared__ float hg_sm[64 * 17];

    const int c   = blockIdx.x;
    const int tid = threadIdx.x;
    const int r   = tid & 63;
    const int g4  = tid >> 6;

    // init state (each CTA its own 8 columns, both layers) into parity 0
    for (int i = tid; i < NLAYER * BATCH * CPC; i += NTH) {
        int l = i >> 9;
        int b = (i >> 3) & 63;
        int j = i & 7;
        int col = c * CPC + j;
        g_S[l][0][b * HID + col] = st0[(size_t)l * BATCH * HID + b * HID + col];
    }
    grid_barrier();

    const int nloc  = g4 * 4;                                   // local col 0..15
    const int nglob = (nloc < 8) ? (c * CPC + nloc)             // global weight col
                                 : (HID + c * CPC + (nloc - 8));

#pragma unroll 1
    for (int t = 0; t < SEQ; t++) {
        const float* xt = x + (size_t)t * BATCH * HID;
#pragma unroll 1
        for (int l = 0; l < NLAYER; l++) {
            // layer input: x_t for layer 0, layer 0's finished state (parity 0) above
            const float* inp = (l == 0) ? xt : g_S[0][0];
#pragma unroll 1
            for (int d = 0; d < NDEPTH; d++) {
                const float* scur = g_S[l][d & 1];
                float*       snxt = g_S[l][(d + 1) & 1];
                const float* W = w_h + (size_t)(l * NDEPTH + d) * HID * TWOH;

                float4 acc = make_float4(0.f, 0.f, 0.f, 0.f);
                gemm_acc(scur, W, s_sm, w_sm, c, tid, acc);
                if (d == 0) {
                    const float* Wi = w_in + (size_t)l * HID * TWOH;
                    gemm_acc(inp, Wi, s_sm, w_sm, c, tid, acc);   // hg0 enters depth 0
                }
                // bias
                const float4 bv = *(const float4*)(
                    b_h + (size_t)(l * NDEPTH + d) * TWOH + nglob);
                acc.x += bv.x; acc.y += bv.y; acc.z += bv.z; acc.w += bv.w;

                // exchange h/g halves through smem, then gated update
                float* hd = hg_sm + r * 17 + nloc;
                hd[0] = acc.x; hd[1] = acc.y; hd[2] = acc.z; hd[3] = acc.w;
                __syncthreads();
                for (int i = tid; i < BATCH * CPC; i += NTH) {
                    int b = i >> 3, j = i & 7;
                    float hh = hg_sm[b * 17 + j];
                    float hg = hg_sm[b * 17 + 8 + j];
                    float hv = tanhf(hh);
                    float gv = 1.0f / (1.0f + expf(-hg));
                    int col = c * CPC + j;
                    float sold = __ldcg(scur + b * HID + col);
                    float sn = fmaf(gv, hv - sold, sold);   // h*g + s*(1-g)
                    snxt[b * HID + col] = sn;
                    if (l == NLAYER - 1 && d == NDEPTH - 1)
                        out[(size_t)t * BATCH * HID + b * HID + col] = sn;
                }
                grid_barrier();
            }
        }
    }

    // final_s (both layers end each timestep at parity 0)
    const size_t fin = (size_t)SEQ * BATCH * HID;
    for (int i = tid; i < NLAYER * BATCH * CPC; i += NTH) {
        int l = i >> 9;
        int b = (i >> 3) & 63;
        int j = i & 7;
        int col = c * CPC + j;
        out[fin + (size_t)l * BATCH * HID + b * HID + col] = g_S[l][0][b * HID + col];
    }
}

// ---------------- launch -------------------------------------------------
extern "C" void kernel_launch(void* const* d_in, const int* in_sizes, int n_in,
                              void* d_out, int out_size) {
    const float* x   = (const float*)d_in[0];   // x      [512,64,1024]
    const float* st  = (const float*)d_in[1];   // state  [2,64,1024]
    const float* wi  = (const float*)d_in[2];   // w_in   [2,1024,2048]
    const float* wh  = (const float*)d_in[3];   // w_h    [2,4,1024,2048]
    const float* bh  = (const float*)d_in[4];   // b_h    [2,4,2048]
    (void)in_sizes; (void)n_in; (void)out_size;
    rhn_kernel<<<GRID, NTH>>>(x, st, wi, wh, bh, (float*)d_out);
}